// round 1
// baseline (speedup 1.0000x reference)
#include <cuda_runtime.h>
#include <cstdint>

// ---------------- problem constants ----------------
#define BATCH   32768
#define C_IN    14
#define NNODES  52
#define H2DIM   128
#define KTOT    (NNODES * H2DIM)   // 6656
#define H1DIM   64
#define CLS     2
#define EPS     1e-5f

#define SPB     8                  // samples per block (kernel A)
#define NBLK_A  (BATCH / SPB)      // 4096

// ---------------- device scratch ----------------
__device__ float g_W01[H2DIM * C_IN];      // fused GAT*GCN weight [128][14]
__device__ float g_b01[H2DIM];
__device__ float g_y[(size_t)BATCH * KTOT]; // 872 MB scratch, pre-BN conv output
__device__ float g_f[(size_t)BATCH * H1DIM];
__device__ float g_stats1[NNODES * 2];     // per-channel sum, sumsq
__device__ float g_stats2[H1DIM * 2];
__device__ float g_bn1[NNODES * 2];        // scale[52], shift[52]
__device__ float g_bn2[H1DIM * 2];         // scale[64], shift[64]

// ---------------- kernel 0: fold weights + zero stats ----------------
__global__ void kPrep(const float* __restrict__ w0, const float* __restrict__ b0,
                      const float* __restrict__ w1, const float* __restrict__ b1) {
    int tid = threadIdx.x;
    for (int e = tid; e < H2DIM * C_IN; e += 256) {
        int lq = e / C_IN, i = e % C_IN;
        float s = 0.f;
        #pragma unroll 8
        for (int c = 0; c < 64; c++) s += w1[lq * 64 + c] * w0[c * C_IN + i];
        g_W01[e] = s;
    }
    for (int lq = tid; lq < H2DIM; lq += 256) {
        float s = b1[lq];
        #pragma unroll 8
        for (int c = 0; c < 64; c++) s += w1[lq * 64 + c] * b0[c];
        g_b01[lq] = s;
    }
    for (int e = tid; e < NNODES * 2; e += 256) g_stats1[e] = 0.f;
    for (int e = tid; e < H1DIM * 2; e += 256)  g_stats2[e] = 0.f;
}

// ---------------- kernel A: fused h2 -> conv mix -> y + stats1 ----------------
__global__ __launch_bounds__(256) void kA(const float* __restrict__ x,
                                          const float* __restrict__ wc,
                                          const float* __restrict__ bc) {
    __shared__ float xs[C_IN * NNODES];        // [14][52]
    __shared__ float h2s[NNODES * H2DIM];      // [52][128]
    __shared__ float wcs[NNODES * NNODES];     // [52][52]
    __shared__ float bcs[NNODES];
    __shared__ float sstat[NNODES * 2];

    const int tid = threadIdx.x;
    const int l = tid & 127;        // feature lane 0..127
    const int z = tid >> 7;         // node parity 0/1

    // register-resident fused weight row
    float wreg[C_IN];
    #pragma unroll
    for (int i = 0; i < C_IN; i++) wreg[i] = g_W01[l * C_IN + i];
    const float b01r = g_b01[l];

    for (int i = tid; i < NNODES * NNODES; i += 256) wcs[i] = wc[i];
    if (tid < NNODES) bcs[tid] = bc[tid];
    if (tid < NNODES * 2) sstat[tid] = 0.f;

    float tsum[26], tssq[26];
    #pragma unroll
    for (int i = 0; i < 26; i++) { tsum[i] = 0.f; tssq[i] = 0.f; }

    const int bbase = blockIdx.x * SPB;
    for (int s = 0; s < SPB; s++) {
        const int b = bbase + s;
        __syncthreads();   // previous iter's conv reads done before xs overwrite
        for (int i = tid; i < C_IN * NNODES; i += 256)
            xs[i] = x[(size_t)b * (C_IN * NNODES) + i];
        __syncthreads();

        // h2[n][l] = relu(sum_i xt[n][i] * W01[l][i] + b01[l])
        #pragma unroll
        for (int idx = 0; idx < 26; idx++) {
            const int n = z + 2 * idx;
            float acc = b01r;
            #pragma unroll
            for (int i = 0; i < C_IN; i++) acc += xs[i * NNODES + n] * wreg[i];
            h2s[n * H2DIM + l] = fmaxf(acc, 0.f);
        }
        __syncthreads();

        // y[o][l] = sum_n wc[o][n] * h2[n][l] + bc[o]
        float acc2[26];
        #pragma unroll
        for (int idx = 0; idx < 26; idx++) acc2[idx] = bcs[z + 2 * idx];
        #pragma unroll
        for (int n = 0; n < NNODES; n += 4) {
            const float h0 = h2s[(n + 0) * H2DIM + l];
            const float h1 = h2s[(n + 1) * H2DIM + l];
            const float h2v = h2s[(n + 2) * H2DIM + l];
            const float h3 = h2s[(n + 3) * H2DIM + l];
            #pragma unroll
            for (int idx = 0; idx < 26; idx++) {
                const int o = z + 2 * idx;
                const float4 w4 = *reinterpret_cast<const float4*>(&wcs[o * NNODES + n]);
                acc2[idx] += h0 * w4.x;
                acc2[idx] += h1 * w4.y;
                acc2[idx] += h2v * w4.z;
                acc2[idx] += h3 * w4.w;
            }
        }
        const size_t base = (size_t)b * KTOT;
        #pragma unroll
        for (int idx = 0; idx < 26; idx++) {
            const int o = z + 2 * idx;
            const float v = acc2[idx];
            g_y[base + o * H2DIM + l] = v;
            tsum[idx] += v;
            tssq[idx] += v * v;
        }
    }

    // block-level stats reduction: warp shfl -> shared atomics -> global atomics
    #pragma unroll
    for (int idx = 0; idx < 26; idx++) {
        float s = tsum[idx], q = tssq[idx];
        #pragma unroll
        for (int off = 16; off; off >>= 1) {
            s += __shfl_xor_sync(0xFFFFFFFFu, s, off);
            q += __shfl_xor_sync(0xFFFFFFFFu, q, off);
        }
        if ((tid & 31) == 0) {
            const int o = z + 2 * idx;
            atomicAdd(&sstat[o * 2 + 0], s);
            atomicAdd(&sstat[o * 2 + 1], q);
        }
    }
    __syncthreads();
    if (tid < NNODES * 2) atomicAdd(&g_stats1[tid], sstat[tid]);
}

// ---------------- kernel B/D: finalize batch-norm params ----------------
__global__ void kBNFin(const float* __restrict__ gamma, const float* __restrict__ beta,
                       const float* __restrict__ stats, float* __restrict__ bnout,
                       int nch, float invcnt) {
    int c = threadIdx.x;
    if (c < nch) {
        float mu = stats[c * 2 + 0] * invcnt;
        float var = stats[c * 2 + 1] * invcnt - mu * mu;
        float sc = gamma[c] * rsqrtf(var + EPS);
        bnout[c] = sc;
        bnout[nch + c] = beta[c] - mu * sc;
    }
}

// ---------------- kernel C: f = relu(BN1(y)) @ wf1^T + bf1, + stats2 ----------------
__global__ __launch_bounds__(256) void kC(const float* __restrict__ wf1,
                                          const float* __restrict__ bf1) {
    __shared__ float zs[64][68];
    __shared__ float ws[64][68];
    __shared__ float sstat[H1DIM * 2];

    const int tid = threadIdx.x;
    const int brow0 = blockIdx.x * 64;
    const int tx = tid & 15, ty = tid >> 4;   // tx -> j-group, ty -> b-group
    const int j4 = tx * 4, b4 = ty * 4;
    const int lrow = tid >> 4;                 // 0..15
    const int lcol = (tid & 15) * 4;           // 0..60

    if (tid < H1DIM * 2) sstat[tid] = 0.f;

    float acc[4][4];
    #pragma unroll
    for (int i = 0; i < 4; i++)
        #pragma unroll
        for (int j = 0; j < 4; j++) acc[i][j] = 0.f;

    for (int k0 = 0; k0 < KTOT; k0 += 64) {
        const int o = k0 >> 7;                 // chunk lies in a single node-channel
        const float a = g_bn1[o];
        const float d = g_bn1[NNODES + o];
        __syncthreads();
        #pragma unroll
        for (int r = 0; r < 4; r++) {
            const int rr = lrow + r * 16;
            float4 v = *reinterpret_cast<const float4*>(
                &g_y[(size_t)(brow0 + rr) * KTOT + k0 + lcol]);
            v.x = fmaxf(a * v.x + d, 0.f);
            v.y = fmaxf(a * v.y + d, 0.f);
            v.z = fmaxf(a * v.z + d, 0.f);
            v.w = fmaxf(a * v.w + d, 0.f);
            *reinterpret_cast<float4*>(&zs[rr][lcol]) = v;
            const float4 w = *reinterpret_cast<const float4*>(
                &wf1[(size_t)rr * KTOT + k0 + lcol]);
            *reinterpret_cast<float4*>(&ws[rr][lcol]) = w;
        }
        __syncthreads();
        #pragma unroll
        for (int kk = 0; kk < 64; kk += 4) {
            float4 zv[4], wv[4];
            #pragma unroll
            for (int i = 0; i < 4; i++) {
                zv[i] = *reinterpret_cast<const float4*>(&zs[b4 + i][kk]);
                wv[i] = *reinterpret_cast<const float4*>(&ws[j4 + i][kk]);
            }
            #pragma unroll
            for (int i = 0; i < 4; i++)
                #pragma unroll
                for (int j = 0; j < 4; j++) {
                    acc[i][j] += zv[i].x * wv[j].x;
                    acc[i][j] += zv[i].y * wv[j].y;
                    acc[i][j] += zv[i].z * wv[j].z;
                    acc[i][j] += zv[i].w * wv[j].w;
                }
        }
    }

    // bias, store f, accumulate stats2
    float bj[4];
    #pragma unroll
    for (int j = 0; j < 4; j++) bj[j] = bf1[j4 + j];
    #pragma unroll
    for (int i = 0; i < 4; i++) {
        float4 out;
        out.x = acc[i][0] + bj[0];
        out.y = acc[i][1] + bj[1];
        out.z = acc[i][2] + bj[2];
        out.w = acc[i][3] + bj[3];
        *reinterpret_cast<float4*>(&g_f[(size_t)(brow0 + b4 + i) * H1DIM + j4]) = out;
        acc[i][0] = out.x; acc[i][1] = out.y; acc[i][2] = out.z; acc[i][3] = out.w;
    }
    #pragma unroll
    for (int j = 0; j < 4; j++) {
        float s = 0.f, q = 0.f;
        #pragma unroll
        for (int i = 0; i < 4; i++) { s += acc[i][j]; q += acc[i][j] * acc[i][j]; }
        atomicAdd(&sstat[(j4 + j) * 2 + 0], s);
        atomicAdd(&sstat[(j4 + j) * 2 + 1], q);
    }
    __syncthreads();
    if (tid < H1DIM * 2) atomicAdd(&g_stats2[tid], sstat[tid]);
}

// ---------------- kernel E: out = relu(BN2(f)) @ wf2^T + bf2 ----------------
__global__ __launch_bounds__(256) void kE(const float* __restrict__ wf2,
                                          const float* __restrict__ bf2,
                                          float* __restrict__ out) {
    __shared__ float w2s[CLS * H1DIM];
    __shared__ float bn2s[H1DIM * 2];
    const int tid = threadIdx.x;
    if (tid < CLS * H1DIM) w2s[tid] = wf2[tid];
    if (tid < H1DIM * 2) bn2s[tid] = g_bn2[tid];
    __syncthreads();
    const int b = blockIdx.x * 256 + tid;
    float a0 = bf2[0], a1 = bf2[1];
    #pragma unroll
    for (int j = 0; j < H1DIM; j += 4) {
        const float4 fv = *reinterpret_cast<const float4*>(&g_f[(size_t)b * H1DIM + j]);
        const float zv0 = fmaxf(bn2s[j + 0] * fv.x + bn2s[H1DIM + j + 0], 0.f);
        const float zv1 = fmaxf(bn2s[j + 1] * fv.y + bn2s[H1DIM + j + 1], 0.f);
        const float zv2 = fmaxf(bn2s[j + 2] * fv.z + bn2s[H1DIM + j + 2], 0.f);
        const float zv3 = fmaxf(bn2s[j + 3] * fv.w + bn2s[H1DIM + j + 3], 0.f);
        a0 += zv0 * w2s[j] + zv1 * w2s[j + 1] + zv2 * w2s[j + 2] + zv3 * w2s[j + 3];
        a1 += zv0 * w2s[H1DIM + j] + zv1 * w2s[H1DIM + j + 1]
            + zv2 * w2s[H1DIM + j + 2] + zv3 * w2s[H1DIM + j + 3];
    }
    out[(size_t)b * CLS + 0] = a0;
    out[(size_t)b * CLS + 1] = a1;
}

// ---------------- launcher ----------------
extern "C" void kernel_launch(void* const* d_in, const int* in_sizes, int n_in,
                              void* d_out, int out_size) {
    const float* x   = (const float*)d_in[0];
    const float* w0  = (const float*)d_in[1];
    const float* b0  = (const float*)d_in[2];
    const float* w1  = (const float*)d_in[3];
    const float* b1  = (const float*)d_in[4];
    const float* wc  = (const float*)d_in[5];
    const float* bc  = (const float*)d_in[6];
    const float* g1  = (const float*)d_in[7];
    const float* be1 = (const float*)d_in[8];
    const float* wf1 = (const float*)d_in[9];
    const float* bf1 = (const float*)d_in[10];
    const float* g2  = (const float*)d_in[11];
    const float* be2 = (const float*)d_in[12];
    const float* wf2 = (const float*)d_in[13];
    const float* bf2 = (const float*)d_in[14];
    float* out = (float*)d_out;

    float* pStats1; cudaGetSymbolAddress((void**)&pStats1, g_stats1);
    float* pStats2; cudaGetSymbolAddress((void**)&pStats2, g_stats2);
    float* pBn1;    cudaGetSymbolAddress((void**)&pBn1, g_bn1);
    float* pBn2;    cudaGetSymbolAddress((void**)&pBn2, g_bn2);

    kPrep<<<1, 256>>>(w0, b0, w1, b1);
    kA<<<NBLK_A, 256>>>(x, wc, bc);
    kBNFin<<<1, 64>>>(g1, be1, pStats1, pBn1, NNODES, 1.0f / ((float)BATCH * H2DIM));
    kC<<<BATCH / 64, 256>>>(wf1, bf1);
    kBNFin<<<1, 64>>>(g2, be2, pStats2, pBn2, H1DIM, 1.0f / (float)BATCH);
    kE<<<BATCH / 256, 256>>>(wf2, bf2, out);
}

// round 4
// speedup vs baseline: 1.5075x; 1.5075x over previous
#include <cuda_runtime.h>
#include <cstdint>

// ---------------- problem constants ----------------
#define BATCH   32768
#define C_IN    14
#define NNODES  52
#define H2DIM   128
#define KTOT    (NNODES * H2DIM)   // 6656
#define H1DIM   64
#define CLS     2
#define EPS     1e-5f

#define SPB     8                  // samples per block (kernel A)
#define NBLK_A  (BATCH / SPB)      // 4096

// kC tiling
#define KC      16                 // k-chunk
#define SZ      20                 // padded smem row stride (conflict-free frag gathers)

// ---------------- device scratch ----------------
__device__ float g_W01[H2DIM * C_IN];      // fused GAT*GCN weight [128][14]
__device__ float g_b01[H2DIM];
__device__ float g_y[(size_t)BATCH * KTOT]; // 872 MB scratch, pre-BN conv output
__device__ float g_f[(size_t)BATCH * H1DIM];
__device__ float g_stats1[NNODES * 2];     // per-channel sum, sumsq
__device__ float g_stats2[H1DIM * 2];
__device__ float g_bn1[NNODES * 2];        // scale[52], shift[52]
__device__ float g_bn2[H1DIM * 2];         // scale[64], shift[64]

// ---------------- kernel 0: fold weights + zero stats ----------------
__global__ void kPrep(const float* __restrict__ w0, const float* __restrict__ b0,
                      const float* __restrict__ w1, const float* __restrict__ b1) {
    int tid = threadIdx.x;
    for (int e = tid; e < H2DIM * C_IN; e += 256) {
        int lq = e / C_IN, i = e % C_IN;
        float s = 0.f;
        #pragma unroll 8
        for (int c = 0; c < 64; c++) s += w1[lq * 64 + c] * w0[c * C_IN + i];
        g_W01[e] = s;
    }
    for (int lq = tid; lq < H2DIM; lq += 256) {
        float s = b1[lq];
        #pragma unroll 8
        for (int c = 0; c < 64; c++) s += w1[lq * 64 + c] * b0[c];
        g_b01[lq] = s;
    }
    for (int e = tid; e < NNODES * 2; e += 256) g_stats1[e] = 0.f;
    for (int e = tid; e < H1DIM * 2; e += 256)  g_stats2[e] = 0.f;
}

// ---------------- kernel A: fused h2 -> conv mix -> y + stats1 ----------------
__global__ __launch_bounds__(256) void kA(const float* __restrict__ x,
                                          const float* __restrict__ wc,
                                          const float* __restrict__ bc) {
    __shared__ float xs[C_IN * NNODES];        // [14][52]
    __shared__ float h2s[NNODES * H2DIM];      // [52][128]
    __shared__ float wcs[NNODES * NNODES];     // [52][52]
    __shared__ float bcs[NNODES];
    __shared__ float sstat[NNODES * 2];

    const int tid = threadIdx.x;
    const int l = tid & 127;        // feature lane 0..127
    const int z = tid >> 7;         // node parity 0/1

    float wreg[C_IN];
    #pragma unroll
    for (int i = 0; i < C_IN; i++) wreg[i] = g_W01[l * C_IN + i];
    const float b01r = g_b01[l];

    for (int i = tid; i < NNODES * NNODES; i += 256) wcs[i] = wc[i];
    if (tid < NNODES) bcs[tid] = bc[tid];
    if (tid < NNODES * 2) sstat[tid] = 0.f;

    float tsum[26], tssq[26];
    #pragma unroll
    for (int i = 0; i < 26; i++) { tsum[i] = 0.f; tssq[i] = 0.f; }

    const int bbase = blockIdx.x * SPB;
    for (int s = 0; s < SPB; s++) {
        const int b = bbase + s;
        __syncthreads();
        for (int i = tid; i < C_IN * NNODES; i += 256)
            xs[i] = x[(size_t)b * (C_IN * NNODES) + i];
        __syncthreads();

        #pragma unroll
        for (int idx = 0; idx < 26; idx++) {
            const int n = z + 2 * idx;
            float acc = b01r;
            #pragma unroll
            for (int i = 0; i < C_IN; i++) acc += xs[i * NNODES + n] * wreg[i];
            h2s[n * H2DIM + l] = fmaxf(acc, 0.f);
        }
        __syncthreads();

        float acc2[26];
        #pragma unroll
        for (int idx = 0; idx < 26; idx++) acc2[idx] = bcs[z + 2 * idx];
        #pragma unroll
        for (int n = 0; n < NNODES; n += 4) {
            const float h0 = h2s[(n + 0) * H2DIM + l];
            const float h1 = h2s[(n + 1) * H2DIM + l];
            const float h2v = h2s[(n + 2) * H2DIM + l];
            const float h3 = h2s[(n + 3) * H2DIM + l];
            #pragma unroll
            for (int idx = 0; idx < 26; idx++) {
                const int o = z + 2 * idx;
                const float4 w4 = *reinterpret_cast<const float4*>(&wcs[o * NNODES + n]);
                acc2[idx] += h0 * w4.x;
                acc2[idx] += h1 * w4.y;
                acc2[idx] += h2v * w4.z;
                acc2[idx] += h3 * w4.w;
            }
        }
        const size_t base = (size_t)b * KTOT;
        #pragma unroll
        for (int idx = 0; idx < 26; idx++) {
            const int o = z + 2 * idx;
            const float v = acc2[idx];
            g_y[base + o * H2DIM + l] = v;
            tsum[idx] += v;
            tssq[idx] += v * v;
        }
    }

    #pragma unroll
    for (int idx = 0; idx < 26; idx++) {
        float s = tsum[idx], q = tssq[idx];
        #pragma unroll
        for (int off = 16; off; off >>= 1) {
            s += __shfl_xor_sync(0xFFFFFFFFu, s, off);
            q += __shfl_xor_sync(0xFFFFFFFFu, q, off);
        }
        if ((tid & 31) == 0) {
            const int o = z + 2 * idx;
            atomicAdd(&sstat[o * 2 + 0], s);
            atomicAdd(&sstat[o * 2 + 1], q);
        }
    }
    __syncthreads();
    if (tid < NNODES * 2) atomicAdd(&g_stats1[tid], sstat[tid]);
}

// ---------------- kernel B/D: finalize batch-norm params ----------------
__global__ void kBNFin(const float* __restrict__ gamma, const float* __restrict__ beta,
                       const float* __restrict__ stats, float* __restrict__ bnout,
                       int nch, float invcnt) {
    int c = threadIdx.x;
    if (c < nch) {
        float mu = stats[c * 2 + 0] * invcnt;
        float var = stats[c * 2 + 1] * invcnt - mu * mu;
        float sc = gamma[c] * rsqrtf(var + EPS);
        bnout[c] = sc;
        bnout[nch + c] = beta[c] - mu * sc;
    }
}

// ---------------- tf32 helpers ----------------
__device__ __forceinline__ uint32_t f2tf(float x) {
    uint32_t u;
    asm("cvt.rna.tf32.f32 %0, %1;" : "=r"(u) : "f"(x));
    return u;
}

#define MMA_T(acc, a, b0v, b1v)                                              \
    asm volatile(                                                            \
        "mma.sync.aligned.m16n8k8.row.col.f32.tf32.tf32.f32 "                \
        "{%0,%1,%2,%3},{%4,%5,%6,%7},{%8,%9},{%0,%1,%2,%3};"                 \
        : "+f"(acc[0]), "+f"(acc[1]), "+f"(acc[2]), "+f"(acc[3])             \
        : "r"(a[0]), "r"(a[1]), "r"(a[2]), "r"(a[3]), "r"(b0v), "r"(b1v))

// ---------------- kernel C: f = relu(BN1(y)) @ wf1^T + bf1 (3xTF32 mma) ----------------
__global__ __launch_bounds__(256, 2) void kC(const float* __restrict__ wf1,
                                             const float* __restrict__ bf1) {
    __shared__ float zhi[128 * SZ];
    __shared__ float zlo[128 * SZ];
    __shared__ float whi[64 * SZ];
    __shared__ float wlo[64 * SZ];
    __shared__ float sstat[H1DIM * 2];

    const int tid = threadIdx.x;
    const int brow0 = blockIdx.x * 128;
    // loader mapping: lr = row (0..63), lc = 4-float column offset in chunk
    const int lr = tid >> 2;
    const int lc = (tid & 3) * 4;
    // mma mapping
    const int warp = tid >> 5, lane = tid & 31;
    const int wm = warp >> 1, wn = warp & 1;    // 4 x 2 warp grid
    const int qr = lane >> 2, qc = lane & 3;

    if (tid < H1DIM * 2) sstat[tid] = 0.f;

    float acc[2][4][4];
    #pragma unroll
    for (int im = 0; im < 2; im++)
        #pragma unroll
        for (int in = 0; in < 4; in++)
            #pragma unroll
            for (int r = 0; r < 4; r++) acc[im][in][r] = 0.f;

    float4 pz0, pz1, pw;

    // prefetch global chunk -> registers (BN1 + ReLU applied inline)
    auto ldg = [&](int k0) {
        const int o = k0 >> 7;
        const float a = g_bn1[o];
        const float d = g_bn1[NNODES + o];
        float4 v0 = *reinterpret_cast<const float4*>(
            &g_y[(size_t)(brow0 + lr) * KTOT + k0 + lc]);
        float4 v1 = *reinterpret_cast<const float4*>(
            &g_y[(size_t)(brow0 + 64 + lr) * KTOT + k0 + lc]);
        pz0.x = fmaxf(a * v0.x + d, 0.f); pz0.y = fmaxf(a * v0.y + d, 0.f);
        pz0.z = fmaxf(a * v0.z + d, 0.f); pz0.w = fmaxf(a * v0.w + d, 0.f);
        pz1.x = fmaxf(a * v1.x + d, 0.f); pz1.y = fmaxf(a * v1.y + d, 0.f);
        pz1.z = fmaxf(a * v1.z + d, 0.f); pz1.w = fmaxf(a * v1.w + d, 0.f);
        pw = *reinterpret_cast<const float4*>(&wf1[(size_t)lr * KTOT + k0 + lc]);
    };

    // split into tf32 hi/lo and store to smem
    auto put = [&](float4 v, float* hs, float* ls, int row) {
        float4 h, l;
        h.x = __uint_as_float(f2tf(v.x)); l.x = __uint_as_float(f2tf(v.x - h.x));
        h.y = __uint_as_float(f2tf(v.y)); l.y = __uint_as_float(f2tf(v.y - h.y));
        h.z = __uint_as_float(f2tf(v.z)); l.z = __uint_as_float(f2tf(v.z - h.z));
        h.w = __uint_as_float(f2tf(v.w)); l.w = __uint_as_float(f2tf(v.w - h.w));
        *reinterpret_cast<float4*>(&hs[row * SZ + lc]) = h;
        *reinterpret_cast<float4*>(&ls[row * SZ + lc]) = l;
    };

    ldg(0);
    const int NCHUNK = KTOT / KC;   // 416
    for (int c = 0; c < NCHUNK; c++) {
        put(pz0, zhi, zlo, lr);
        put(pz1, zhi, zlo, lr + 64);
        put(pw, whi, wlo, lr);
        __syncthreads();
        if (c + 1 < NCHUNK) ldg((c + 1) * KC);   // overlap global latency w/ compute

        #pragma unroll
        for (int k8 = 0; k8 < 2; k8++) {
            const int col = k8 * 8 + qc;
            uint32_t ah[2][4], al[2][4];
            #pragma unroll
            for (int im = 0; im < 2; im++) {
                const int m = wm * 32 + im * 16 + qr;
                ah[im][0] = __float_as_uint(zhi[m * SZ + col]);
                ah[im][1] = __float_as_uint(zhi[(m + 8) * SZ + col]);
                ah[im][2] = __float_as_uint(zhi[m * SZ + col + 4]);
                ah[im][3] = __float_as_uint(zhi[(m + 8) * SZ + col + 4]);
                al[im][0] = __float_as_uint(zlo[m * SZ + col]);
                al[im][1] = __float_as_uint(zlo[(m + 8) * SZ + col]);
                al[im][2] = __float_as_uint(zlo[m * SZ + col + 4]);
                al[im][3] = __float_as_uint(zlo[(m + 8) * SZ + col + 4]);
            }
            #pragma unroll
            for (int in = 0; in < 4; in++) {
                const int n = wn * 32 + in * 8 + qr;
                const uint32_t bh0 = __float_as_uint(whi[n * SZ + col]);
                const uint32_t bh1 = __float_as_uint(whi[n * SZ + col + 4]);
                const uint32_t bl0 = __float_as_uint(wlo[n * SZ + col]);
                const uint32_t bl1 = __float_as_uint(wlo[n * SZ + col + 4]);
                #pragma unroll
                for (int im = 0; im < 2; im++) {
                    MMA_T(acc[im][in], ah[im], bh0, bh1);   // hi*hi
                    MMA_T(acc[im][in], ah[im], bl0, bl1);   // hi*lo
                    MMA_T(acc[im][in], al[im], bh0, bh1);   // lo*hi
                }
            }
        }
        __syncthreads();
    }

    // epilogue: bias, store f, stats2
    #pragma unroll
    for (int in = 0; in < 4; in++) {
        const int c0 = wn * 32 + in * 8 + 2 * qc;
        const float bv0 = bf1[c0], bv1 = bf1[c0 + 1];
        float s0 = 0.f, q0 = 0.f, s1 = 0.f, q1 = 0.f;
        #pragma unroll
        for (int im = 0; im < 2; im++) {
            const int r0 = brow0 + wm * 32 + im * 16 + qr;
            const float v0 = acc[im][in][0] + bv0;
            const float v1 = acc[im][in][1] + bv1;
            const float v2 = acc[im][in][2] + bv0;
            const float v3 = acc[im][in][3] + bv1;
            g_f[(size_t)r0 * H1DIM + c0]           = v0;
            g_f[(size_t)r0 * H1DIM + c0 + 1]       = v1;
            g_f[(size_t)(r0 + 8) * H1DIM + c0]     = v2;
            g_f[(size_t)(r0 + 8) * H1DIM + c0 + 1] = v3;
            s0 += v0 + v2; q0 += v0 * v0 + v2 * v2;
            s1 += v1 + v3; q1 += v1 * v1 + v3 * v3;
        }
        #pragma unroll
        for (int off = 4; off < 32; off <<= 1) {
            s0 += __shfl_xor_sync(0xFFFFFFFFu, s0, off);
            q0 += __shfl_xor_sync(0xFFFFFFFFu, q0, off);
            s1 += __shfl_xor_sync(0xFFFFFFFFu, s1, off);
            q1 += __shfl_xor_sync(0xFFFFFFFFu, q1, off);
        }
        if (qr == 0) {
            atomicAdd(&sstat[2 * c0 + 0], s0);
            atomicAdd(&sstat[2 * c0 + 1], q0);
            atomicAdd(&sstat[2 * (c0 + 1) + 0], s1);
            atomicAdd(&sstat[2 * (c0 + 1) + 1], q1);
        }
    }
    __syncthreads();
    if (tid < H1DIM * 2) atomicAdd(&g_stats2[tid], sstat[tid]);
}

// ---------------- kernel E: out = relu(BN2(f)) @ wf2^T + bf2 ----------------
__global__ __launch_bounds__(256) void kE(const float* __restrict__ wf2,
                                          const float* __restrict__ bf2,
                                          float* __restrict__ out) {
    __shared__ float w2s[CLS * H1DIM];
    __shared__ float bn2s[H1DIM * 2];
    const int tid = threadIdx.x;
    if (tid < CLS * H1DIM) w2s[tid] = wf2[tid];
    if (tid < H1DIM * 2) bn2s[tid] = g_bn2[tid];
    __syncthreads();
    const int b = blockIdx.x * 256 + tid;
    float a0 = bf2[0], a1 = bf2[1];
    #pragma unroll
    for (int j = 0; j < H1DIM; j += 4) {
        const float4 fv = *reinterpret_cast<const float4*>(&g_f[(size_t)b * H1DIM + j]);
        const float zv0 = fmaxf(bn2s[j + 0] * fv.x + bn2s[H1DIM + j + 0], 0.f);
        const float zv1 = fmaxf(bn2s[j + 1] * fv.y + bn2s[H1DIM + j + 1], 0.f);
        const float zv2 = fmaxf(bn2s[j + 2] * fv.z + bn2s[H1DIM + j + 2], 0.f);
        const float zv3 = fmaxf(bn2s[j + 3] * fv.w + bn2s[H1DIM + j + 3], 0.f);
        a0 += zv0 * w2s[j] + zv1 * w2s[j + 1] + zv2 * w2s[j + 2] + zv3 * w2s[j + 3];
        a1 += zv0 * w2s[H1DIM + j] + zv1 * w2s[H1DIM + j + 1]
            + zv2 * w2s[H1DIM + j + 2] + zv3 * w2s[H1DIM + j + 3];
    }
    out[(size_t)b * CLS + 0] = a0;
    out[(size_t)b * CLS + 1] = a1;
}

// ---------------- launcher ----------------
extern "C" void kernel_launch(void* const* d_in, const int* in_sizes, int n_in,
                              void* d_out, int out_size) {
    const float* x   = (const float*)d_in[0];
    const float* w0  = (const float*)d_in[1];
    const float* b0  = (const float*)d_in[2];
    const float* w1  = (const float*)d_in[3];
    const float* b1  = (const float*)d_in[4];
    const float* wc  = (const float*)d_in[5];
    const float* bc  = (const float*)d_in[6];
    const float* g1  = (const float*)d_in[7];
    const float* be1 = (const float*)d_in[8];
    const float* wf1 = (const float*)d_in[9];
    const float* bf1 = (const float*)d_in[10];
    const float* g2  = (const float*)d_in[11];
    const float* be2 = (const float*)d_in[12];
    const float* wf2 = (const float*)d_in[13];
    const float* bf2 = (const float*)d_in[14];
    float* out = (float*)d_out;

    float* pStats1; cudaGetSymbolAddress((void**)&pStats1, g_stats1);
    float* pStats2; cudaGetSymbolAddress((void**)&pStats2, g_stats2);
    float* pBn1;    cudaGetSymbolAddress((void**)&pBn1, g_bn1);
    float* pBn2;    cudaGetSymbolAddress((void**)&pBn2, g_bn2);

    kPrep<<<1, 256>>>(w0, b0, w1, b1);
    kA<<<NBLK_A, 256>>>(x, wc, bc);
    kBNFin<<<1, 64>>>(g1, be1, pStats1, pBn1, NNODES, 1.0f / ((float)BATCH * H2DIM));
    kC<<<BATCH / 128, 256>>>(wf1, bf1);
    kBNFin<<<1, 64>>>(g2, be2, pStats2, pBn2, H1DIM, 1.0f / (float)BATCH);
    kE<<<BATCH / 256, 256>>>(wf2, bf2, out);
}

// round 5
// speedup vs baseline: 1.8069x; 1.1986x over previous
#include <cuda_runtime.h>
#include <cstdint>

// ---------------- problem constants ----------------
#define BATCH   32768
#define C_IN    14
#define NNODES  52
#define H2DIM   128
#define KTOT    (NNODES * H2DIM)   // 6656
#define H1DIM   64
#define CLS     2
#define EPS     1e-5f

#define SPB     8                  // samples per block (kernel A)
#define NBLK_A  (BATCH / SPB)      // 4096

// kC tiling
#define KC      16                 // k-chunk
#define SZ      20                 // padded smem row stride (conflict-free frag gathers)

// kA smem layout (floats), dynamic
#define KA_XS     0                // 728 -> pad 736
#define KA_H2HI   736              // 56 x 132 = 7392
#define KA_H2LO   (736 + 7392)
#define KA_SSTAT  (736 + 7392 + 7392)
#define KA_SMEMF  (736 + 7392 + 7392 + 104)
#define KA_HSTRIDE 132

// ---------------- device scratch ----------------
__device__ float g_W01[H2DIM * C_IN];      // fused GAT*GCN weight [128][14]
__device__ float g_b01[H2DIM];
__device__ float g_y[(size_t)BATCH * KTOT]; // 872 MB scratch, pre-BN conv output
__device__ float g_f[(size_t)BATCH * H1DIM];
__device__ float g_stats1[NNODES * 2];     // per-channel sum, sumsq
__device__ float g_stats2[H1DIM * 2];
__device__ float g_bn1[NNODES * 2];        // scale[52], shift[52]
__device__ float g_bn2[H1DIM * 2];         // scale[64], shift[64]

// ---------------- kernel 0: fold weights + zero stats ----------------
__global__ void kPrep(const float* __restrict__ w0, const float* __restrict__ b0,
                      const float* __restrict__ w1, const float* __restrict__ b1) {
    int tid = threadIdx.x;
    for (int e = tid; e < H2DIM * C_IN; e += 256) {
        int lq = e / C_IN, i = e % C_IN;
        float s = 0.f;
        #pragma unroll 8
        for (int c = 0; c < 64; c++) s += w1[lq * 64 + c] * w0[c * C_IN + i];
        g_W01[e] = s;
    }
    for (int lq = tid; lq < H2DIM; lq += 256) {
        float s = b1[lq];
        #pragma unroll 8
        for (int c = 0; c < 64; c++) s += w1[lq * 64 + c] * b0[c];
        g_b01[lq] = s;
    }
    for (int e = tid; e < NNODES * 2; e += 256) g_stats1[e] = 0.f;
    for (int e = tid; e < H1DIM * 2; e += 256)  g_stats2[e] = 0.f;
}

// ---------------- tf32 helpers ----------------
__device__ __forceinline__ uint32_t f2tf(float x) {
    uint32_t u;
    asm("cvt.rna.tf32.f32 %0, %1;" : "=r"(u) : "f"(x));
    return u;
}

#define MMA_T(acc, a, b0v, b1v)                                              \
    asm volatile(                                                            \
        "mma.sync.aligned.m16n8k8.row.col.f32.tf32.tf32.f32 "                \
        "{%0,%1,%2,%3},{%4,%5,%6,%7},{%8,%9},{%0,%1,%2,%3};"                 \
        : "+f"(acc[0]), "+f"(acc[1]), "+f"(acc[2]), "+f"(acc[3])             \
        : "r"(a[0]), "r"(a[1]), "r"(a[2]), "r"(a[3]), "r"(b0v), "r"(b1v))

// ---------------- kernel A (v2): fused h2 -> conv via 3xTF32 MMA -> y + stats1 ----
// 512 threads = 16 warps: warp = mt (m16 o-tile, 0..3) x nq (n32 l-quarter, 0..3)
__global__ __launch_bounds__(512) void kA(const float* __restrict__ x,
                                          const float* __restrict__ wc,
                                          const float* __restrict__ bc) {
    extern __shared__ float smem[];
    float* xs    = smem + KA_XS;       // [14][52]
    float* h2hi  = smem + KA_H2HI;     // [56][132] tf32-hi of relu(h2)
    float* h2lo  = smem + KA_H2LO;     // [56][132] tf32-lo
    float* sstat = smem + KA_SSTAT;    // [52*2]

    const int tid  = threadIdx.x;
    const int warp = tid >> 5, lane = tid & 31;
    const int mt = warp >> 2, nq = warp & 3;
    const int qr = lane >> 2, qc = lane & 3;
    const int rA = mt * 16 + qr, rB = rA + 8;

    // writer mapping for h2 stage
    const int wl = tid & 127;          // feature lane 0..127
    const int wz = tid >> 7;           // node group 0..3

    // ---- one-time setup ----
    // register-cached A fragments of wc (hi/lo split), 7 k8 steps
    uint32_t ahi[7][4], alo[7][4];
    #pragma unroll
    for (int k8 = 0; k8 < 7; k8++) {
        const int k0 = 8 * k8 + qc, k1 = k0 + 4;
        float a00 = (rA < NNODES && k0 < NNODES) ? wc[rA * NNODES + k0] : 0.f;
        float a10 = (rB < NNODES && k0 < NNODES) ? wc[rB * NNODES + k0] : 0.f;
        float a01 = (rA < NNODES && k1 < NNODES) ? wc[rA * NNODES + k1] : 0.f;
        float a11 = (rB < NNODES && k1 < NNODES) ? wc[rB * NNODES + k1] : 0.f;
        ahi[k8][0] = f2tf(a00); alo[k8][0] = f2tf(a00 - __uint_as_float(ahi[k8][0]));
        ahi[k8][1] = f2tf(a10); alo[k8][1] = f2tf(a10 - __uint_as_float(ahi[k8][1]));
        ahi[k8][2] = f2tf(a01); alo[k8][2] = f2tf(a01 - __uint_as_float(ahi[k8][2]));
        ahi[k8][3] = f2tf(a11); alo[k8][3] = f2tf(a11 - __uint_as_float(ahi[k8][3]));
    }

    // fused GAT*GCN weight row (for h2 stage)
    float wreg[C_IN];
    #pragma unroll
    for (int i = 0; i < C_IN; i++) wreg[i] = g_W01[wl * C_IN + i];
    const float b01r = g_b01[wl];

    const float biasA = (rA < NNODES) ? bc[rA] : 0.f;
    const float biasB = (rB < NNODES) ? bc[rB] : 0.f;

    // zero pad rows 52..55 of h2 (never written again) + stats
    for (int i = tid; i < 4 * KA_HSTRIDE; i += 512) {
        h2hi[NNODES * KA_HSTRIDE + i] = 0.f;
        h2lo[NNODES * KA_HSTRIDE + i] = 0.f;
    }
    if (tid < NNODES * 2) sstat[tid] = 0.f;

    float s0 = 0.f, q0 = 0.f, s1 = 0.f, q1 = 0.f;   // per-thread stats (rows rA, rB)

    const int bbase = blockIdx.x * SPB;
    for (int s = 0; s < SPB; s++) {
        const int b = bbase + s;
        __syncthreads();   // all conv reads of previous sample's h2 done
        for (int i = tid; i < C_IN * NNODES; i += 512)
            xs[i] = x[(size_t)b * (C_IN * NNODES) + i];
        __syncthreads();

        // h2[n][l] = relu(sum_i xt[n][i]*W01[l][i] + b01[l]), split hi/lo
        #pragma unroll
        for (int idx = 0; idx < 13; idx++) {
            const int n = wz + 4 * idx;
            float acc = b01r;
            #pragma unroll
            for (int i = 0; i < C_IN; i++) acc += xs[i * NNODES + n] * wreg[i];
            const float v = fmaxf(acc, 0.f);
            const uint32_t hu = f2tf(v);
            const float hf = __uint_as_float(hu);
            h2hi[n * KA_HSTRIDE + wl] = hf;
            h2lo[n * KA_HSTRIDE + wl] = __uint_as_float(f2tf(v - hf));
        }
        __syncthreads();

        // conv: y[o][l] = sum_n wc[o][n]*h2[n][l] + bc[o], 3xTF32 MMA
        float c[4][4];
        #pragma unroll
        for (int t = 0; t < 4; t++) {
            c[t][0] = biasA; c[t][1] = biasA;
            c[t][2] = biasB; c[t][3] = biasB;
        }
        #pragma unroll
        for (int k8 = 0; k8 < 7; k8++) {
            const int r0 = (8 * k8 + qc) * KA_HSTRIDE;
            const int r1 = r0 + 4 * KA_HSTRIDE;
            #pragma unroll
            for (int t = 0; t < 4; t++) {
                const int l = nq * 32 + t * 8 + qr;
                const uint32_t bh0 = __float_as_uint(h2hi[r0 + l]);
                const uint32_t bh1 = __float_as_uint(h2hi[r1 + l]);
                const uint32_t bl0 = __float_as_uint(h2lo[r0 + l]);
                const uint32_t bl1 = __float_as_uint(h2lo[r1 + l]);
                MMA_T(c[t], ahi[k8], bh0, bh1);   // hi*hi
                MMA_T(c[t], ahi[k8], bl0, bl1);   // hi*lo
                MMA_T(c[t], alo[k8], bh0, bh1);   // lo*hi
            }
        }

        // epilogue: store y, accumulate stats
        const size_t base = (size_t)b * KTOT;
        #pragma unroll
        for (int t = 0; t < 4; t++) {
            const int l0 = nq * 32 + t * 8 + 2 * qc;
            if (rA < NNODES) {
                float2 v; v.x = c[t][0]; v.y = c[t][1];
                *reinterpret_cast<float2*>(&g_y[base + rA * H2DIM + l0]) = v;
                s0 += v.x + v.y; q0 += v.x * v.x + v.y * v.y;
            }
            if (rB < NNODES) {
                float2 v; v.x = c[t][2]; v.y = c[t][3];
                *reinterpret_cast<float2*>(&g_y[base + rB * H2DIM + l0]) = v;
                s1 += v.x + v.y; q1 += v.x * v.x + v.y * v.y;
            }
        }
    }

    // stats reduce: quad (qc) shfl -> shared atomics -> global atomics
    s0 += __shfl_xor_sync(0xFFFFFFFFu, s0, 1); s0 += __shfl_xor_sync(0xFFFFFFFFu, s0, 2);
    q0 += __shfl_xor_sync(0xFFFFFFFFu, q0, 1); q0 += __shfl_xor_sync(0xFFFFFFFFu, q0, 2);
    s1 += __shfl_xor_sync(0xFFFFFFFFu, s1, 1); s1 += __shfl_xor_sync(0xFFFFFFFFu, s1, 2);
    q1 += __shfl_xor_sync(0xFFFFFFFFu, q1, 1); q1 += __shfl_xor_sync(0xFFFFFFFFu, q1, 2);
    if (qc == 0) {
        if (rA < NNODES) {
            atomicAdd(&sstat[rA * 2 + 0], s0);
            atomicAdd(&sstat[rA * 2 + 1], q0);
        }
        if (rB < NNODES) {
            atomicAdd(&sstat[rB * 2 + 0], s1);
            atomicAdd(&sstat[rB * 2 + 1], q1);
        }
    }
    __syncthreads();
    if (tid < NNODES * 2) atomicAdd(&g_stats1[tid], sstat[tid]);
}

// ---------------- kernel B/D: finalize batch-norm params ----------------
__global__ void kBNFin(const float* __restrict__ gamma, const float* __restrict__ beta,
                       const float* __restrict__ stats, float* __restrict__ bnout,
                       int nch, float invcnt) {
    int c = threadIdx.x;
    if (c < nch) {
        float mu = stats[c * 2 + 0] * invcnt;
        float var = stats[c * 2 + 1] * invcnt - mu * mu;
        float sc = gamma[c] * rsqrtf(var + EPS);
        bnout[c] = sc;
        bnout[nch + c] = beta[c] - mu * sc;
    }
}

// ---------------- kernel C: f = relu(BN1(y)) @ wf1^T + bf1 (3xTF32 mma) ----------------
__global__ __launch_bounds__(256, 2) void kC(const float* __restrict__ wf1,
                                             const float* __restrict__ bf1) {
    __shared__ float zhi[128 * SZ];
    __shared__ float zlo[128 * SZ];
    __shared__ float whi[64 * SZ];
    __shared__ float wlo[64 * SZ];
    __shared__ float sstat[H1DIM * 2];

    const int tid = threadIdx.x;
    const int brow0 = blockIdx.x * 128;
    const int lr = tid >> 2;
    const int lc = (tid & 3) * 4;
    const int warp = tid >> 5, lane = tid & 31;
    const int wm = warp >> 1, wn = warp & 1;
    const int qr = lane >> 2, qc = lane & 3;

    if (tid < H1DIM * 2) sstat[tid] = 0.f;

    float acc[2][4][4];
    #pragma unroll
    for (int im = 0; im < 2; im++)
        #pragma unroll
        for (int in = 0; in < 4; in++)
            #pragma unroll
            for (int r = 0; r < 4; r++) acc[im][in][r] = 0.f;

    float4 pz0, pz1, pw;

    auto ldg = [&](int k0) {
        const int o = k0 >> 7;
        const float a = g_bn1[o];
        const float d = g_bn1[NNODES + o];
        float4 v0 = *reinterpret_cast<const float4*>(
            &g_y[(size_t)(brow0 + lr) * KTOT + k0 + lc]);
        float4 v1 = *reinterpret_cast<const float4*>(
            &g_y[(size_t)(brow0 + 64 + lr) * KTOT + k0 + lc]);
        pz0.x = fmaxf(a * v0.x + d, 0.f); pz0.y = fmaxf(a * v0.y + d, 0.f);
        pz0.z = fmaxf(a * v0.z + d, 0.f); pz0.w = fmaxf(a * v0.w + d, 0.f);
        pz1.x = fmaxf(a * v1.x + d, 0.f); pz1.y = fmaxf(a * v1.y + d, 0.f);
        pz1.z = fmaxf(a * v1.z + d, 0.f); pz1.w = fmaxf(a * v1.w + d, 0.f);
        pw = *reinterpret_cast<const float4*>(&wf1[(size_t)lr * KTOT + k0 + lc]);
    };

    auto put = [&](float4 v, float* hs, float* ls, int row) {
        float4 h, l;
        h.x = __uint_as_float(f2tf(v.x)); l.x = __uint_as_float(f2tf(v.x - h.x));
        h.y = __uint_as_float(f2tf(v.y)); l.y = __uint_as_float(f2tf(v.y - h.y));
        h.z = __uint_as_float(f2tf(v.z)); l.z = __uint_as_float(f2tf(v.z - h.z));
        h.w = __uint_as_float(f2tf(v.w)); l.w = __uint_as_float(f2tf(v.w - h.w));
        *reinterpret_cast<float4*>(&hs[row * SZ + lc]) = h;
        *reinterpret_cast<float4*>(&ls[row * SZ + lc]) = l;
    };

    ldg(0);
    const int NCHUNK = KTOT / KC;   // 416
    for (int c = 0; c < NCHUNK; c++) {
        put(pz0, zhi, zlo, lr);
        put(pz1, zhi, zlo, lr + 64);
        put(pw, whi, wlo, lr);
        __syncthreads();
        if (c + 1 < NCHUNK) ldg((c + 1) * KC);

        #pragma unroll
        for (int k8 = 0; k8 < 2; k8++) {
            const int col = k8 * 8 + qc;
            uint32_t ah[2][4], al[2][4];
            #pragma unroll
            for (int im = 0; im < 2; im++) {
                const int m = wm * 32 + im * 16 + qr;
                ah[im][0] = __float_as_uint(zhi[m * SZ + col]);
                ah[im][1] = __float_as_uint(zhi[(m + 8) * SZ + col]);
                ah[im][2] = __float_as_uint(zhi[m * SZ + col + 4]);
                ah[im][3] = __float_as_uint(zhi[(m + 8) * SZ + col + 4]);
                al[im][0] = __float_as_uint(zlo[m * SZ + col]);
                al[im][1] = __float_as_uint(zlo[(m + 8) * SZ + col]);
                al[im][2] = __float_as_uint(zlo[m * SZ + col + 4]);
                al[im][3] = __float_as_uint(zlo[(m + 8) * SZ + col + 4]);
            }
            #pragma unroll
            for (int in = 0; in < 4; in++) {
                const int n = wn * 32 + in * 8 + qr;
                const uint32_t bh0 = __float_as_uint(whi[n * SZ + col]);
                const uint32_t bh1 = __float_as_uint(whi[n * SZ + col + 4]);
                const uint32_t bl0 = __float_as_uint(wlo[n * SZ + col]);
                const uint32_t bl1 = __float_as_uint(wlo[n * SZ + col + 4]);
                #pragma unroll
                for (int im = 0; im < 2; im++) {
                    MMA_T(acc[im][in], ah[im], bh0, bh1);
                    MMA_T(acc[im][in], ah[im], bl0, bl1);
                    MMA_T(acc[im][in], al[im], bh0, bh1);
                }
            }
        }
        __syncthreads();
    }

    #pragma unroll
    for (int in = 0; in < 4; in++) {
        const int c0 = wn * 32 + in * 8 + 2 * qc;
        const float bv0 = bf1[c0], bv1 = bf1[c0 + 1];
        float s0 = 0.f, q0 = 0.f, s1 = 0.f, q1 = 0.f;
        #pragma unroll
        for (int im = 0; im < 2; im++) {
            const int r0 = brow0 + wm * 32 + im * 16 + qr;
            const float v0 = acc[im][in][0] + bv0;
            const float v1 = acc[im][in][1] + bv1;
            const float v2 = acc[im][in][2] + bv0;
            const float v3 = acc[im][in][3] + bv1;
            g_f[(size_t)r0 * H1DIM + c0]           = v0;
            g_f[(size_t)r0 * H1DIM + c0 + 1]       = v1;
            g_f[(size_t)(r0 + 8) * H1DIM + c0]     = v2;
            g_f[(size_t)(r0 + 8) * H1DIM + c0 + 1] = v3;
            s0 += v0 + v2; q0 += v0 * v0 + v2 * v2;
            s1 += v1 + v3; q1 += v1 * v1 + v3 * v3;
        }
        #pragma unroll
        for (int off = 4; off < 32; off <<= 1) {
            s0 += __shfl_xor_sync(0xFFFFFFFFu, s0, off);
            q0 += __shfl_xor_sync(0xFFFFFFFFu, q0, off);
            s1 += __shfl_xor_sync(0xFFFFFFFFu, s1, off);
            q1 += __shfl_xor_sync(0xFFFFFFFFu, q1, off);
        }
        if (qr == 0) {
            atomicAdd(&sstat[2 * c0 + 0], s0);
            atomicAdd(&sstat[2 * c0 + 1], q0);
            atomicAdd(&sstat[2 * (c0 + 1) + 0], s1);
            atomicAdd(&sstat[2 * (c0 + 1) + 1], q1);
        }
    }
    __syncthreads();
    if (tid < H1DIM * 2) atomicAdd(&g_stats2[tid], sstat[tid]);
}

// ---------------- kernel E: out = relu(BN2(f)) @ wf2^T + bf2 ----------------
__global__ __launch_bounds__(256) void kE(const float* __restrict__ wf2,
                                          const float* __restrict__ bf2,
                                          float* __restrict__ out) {
    __shared__ float w2s[CLS * H1DIM];
    __shared__ float bn2s[H1DIM * 2];
    const int tid = threadIdx.x;
    if (tid < CLS * H1DIM) w2s[tid] = wf2[tid];
    if (tid < H1DIM * 2) bn2s[tid] = g_bn2[tid];
    __syncthreads();
    const int b = blockIdx.x * 256 + tid;
    float a0 = bf2[0], a1 = bf2[1];
    #pragma unroll
    for (int j = 0; j < H1DIM; j += 4) {
        const float4 fv = *reinterpret_cast<const float4*>(&g_f[(size_t)b * H1DIM + j]);
        const float zv0 = fmaxf(bn2s[j + 0] * fv.x + bn2s[H1DIM + j + 0], 0.f);
        const float zv1 = fmaxf(bn2s[j + 1] * fv.y + bn2s[H1DIM + j + 1], 0.f);
        const float zv2 = fmaxf(bn2s[j + 2] * fv.z + bn2s[H1DIM + j + 2], 0.f);
        const float zv3 = fmaxf(bn2s[j + 3] * fv.w + bn2s[H1DIM + j + 3], 0.f);
        a0 += zv0 * w2s[j] + zv1 * w2s[j + 1] + zv2 * w2s[j + 2] + zv3 * w2s[j + 3];
        a1 += zv0 * w2s[H1DIM + j] + zv1 * w2s[H1DIM + j + 1]
            + zv2 * w2s[H1DIM + j + 2] + zv3 * w2s[H1DIM + j + 3];
    }
    out[(size_t)b * CLS + 0] = a0;
    out[(size_t)b * CLS + 1] = a1;
}

// ---------------- launcher ----------------
extern "C" void kernel_launch(void* const* d_in, const int* in_sizes, int n_in,
                              void* d_out, int out_size) {
    const float* x   = (const float*)d_in[0];
    const float* w0  = (const float*)d_in[1];
    const float* b0  = (const float*)d_in[2];
    const float* w1  = (const float*)d_in[3];
    const float* b1  = (const float*)d_in[4];
    const float* wc  = (const float*)d_in[5];
    const float* bc  = (const float*)d_in[6];
    const float* g1  = (const float*)d_in[7];
    const float* be1 = (const float*)d_in[8];
    const float* wf1 = (const float*)d_in[9];
    const float* bf1 = (const float*)d_in[10];
    const float* g2  = (const float*)d_in[11];
    const float* be2 = (const float*)d_in[12];
    const float* wf2 = (const float*)d_in[13];
    const float* bf2 = (const float*)d_in[14];
    float* out = (float*)d_out;

    float* pStats1; cudaGetSymbolAddress((void**)&pStats1, g_stats1);
    float* pStats2; cudaGetSymbolAddress((void**)&pStats2, g_stats2);
    float* pBn1;    cudaGetSymbolAddress((void**)&pBn1, g_bn1);
    float* pBn2;    cudaGetSymbolAddress((void**)&pBn2, g_bn2);

    const int kaSmem = KA_SMEMF * 4;   // ~62.5 KB dynamic
    cudaFuncSetAttribute(kA, cudaFuncAttributeMaxDynamicSharedMemorySize, kaSmem);

    kPrep<<<1, 256>>>(w0, b0, w1, b1);
    kA<<<NBLK_A, 512, kaSmem>>>(x, wc, bc);
    kBNFin<<<1, 64>>>(g1, be1, pStats1, pBn1, NNODES, 1.0f / ((float)BATCH * H2DIM));
    kC<<<BATCH / 128, 256>>>(wf1, bf1);
    kBNFin<<<1, 64>>>(g2, be2, pStats2, pBn2, H1DIM, 1.0f / (float)BATCH);
    kE<<<BATCH / 256, 256>>>(wf2, bf2, out);
}